// round 3
// baseline (speedup 1.0000x reference)
#include <cuda_runtime.h>

// Problem constants
#define B_    4
#define CIN   256
#define COUT  256
#define CMID  64
#define H_    64
#define W_    64
#define HO    128
#define WO    128

// Scratch (static __device__ allowed; no runtime allocation)
__device__ float g_mid[B_ * CMID * H_ * W_];     // 4 MB: 1x1 bottleneck output
__device__ float g_wth[9 * CIN * COUT];          // 2.25 MB: w_high transposed [t][c][o]
__device__ float g_wtl[9 * CMID * COUT];         // 576 KB: w_low2 transposed [t][c][o]

// ---------------------------------------------------------------------------
// Kernel 0: transpose weights from [C, O, ky, kx] -> [t][c][o] (o contiguous)
// ---------------------------------------------------------------------------
__global__ void transpose_weights_kernel(const float* __restrict__ wh,
                                         const float* __restrict__ wl2) {
    int idx = blockIdx.x * blockDim.x + threadIdx.x;
    const int NH = 9 * CIN * COUT;
    const int NL = 9 * CMID * COUT;
    if (idx < NH) {
        int t = idx / (CIN * COUT);
        int rem = idx - t * (CIN * COUT);
        int c = rem / COUT;
        int o = rem - c * COUT;
        g_wth[idx] = wh[(c * COUT + o) * 9 + t];
    }
    if (idx < NL) {
        int t = idx / (CMID * COUT);
        int rem = idx - t * (CMID * COUT);
        int c = rem / COUT;
        int o = rem - c * COUT;
        g_wtl[idx] = wl2[(c * COUT + o) * 9 + t];
    }
}

// ---------------------------------------------------------------------------
// Kernel 1: 1x1 bottleneck  mid[b,m,y,x] = sum_c w1[m,c]*inx[b,c,y,x] + b1[m]
// Block = (b, y) row; 256 threads; smem-tiled K over 256.
// ---------------------------------------------------------------------------
__global__ void __launch_bounds__(256) mid_kernel(const float* __restrict__ inx,
                                                  const float* __restrict__ w1,
                                                  const float* __restrict__ b1) {
    __shared__ float Xs[16][64];
    __shared__ float Ws[16][64];
    const int b = blockIdx.x >> 6;
    const int y = blockIdx.x & 63;
    const int tid = threadIdx.x;
    const int x = tid & 63;
    const int mg = tid >> 6;   // 0..3 -> 16 m values each

    float acc[16];
#pragma unroll
    for (int i = 0; i < 16; i++) acc[i] = 0.f;

    for (int c0 = 0; c0 < CIN; c0 += 16) {
#pragma unroll
        for (int r = 0; r < 4; r++) {
            int e = tid + 256 * r;
            int k = e >> 6;
            int s = e & 63;
            Xs[k][s] = inx[((b * CIN + c0 + k) * H_ + y) * W_ + s];
            Ws[k][s] = w1[s * CIN + c0 + k];   // s = m here (CMID=64)
        }
        __syncthreads();
#pragma unroll
        for (int k = 0; k < 16; k++) {
            float xv = Xs[k][x];
#pragma unroll
            for (int i = 0; i < 16; i++)
                acc[i] = fmaf(Ws[k][mg * 16 + i], xv, acc[i]);
        }
        __syncthreads();
    }
#pragma unroll
    for (int i = 0; i < 16; i++) {
        int m = mg * 16 + i;
        g_mid[((b * CMID + m) * H_ + y) * W_ + x] = acc[i] + b1[m];
    }
}

// ---------------------------------------------------------------------------
// Kernel 2: main implicit GEMM over parity-decomposed transposed conv.
// Block: (iy, b*4+parity, cout_tile). Computes 64 couts x 64 output cols
// (one full output row of its parity), both branches, mask-select epilogue.
// ---------------------------------------------------------------------------
__global__ void __launch_bounds__(256) tconv_main_kernel(
    const float* __restrict__ inx,
    const float* __restrict__ mask,
    const float* __restrict__ inv_mask,
    const float* __restrict__ bh,
    const float* __restrict__ bl2,
    float* __restrict__ out) {
    __shared__ __align__(16) float As[16][64];
    __shared__ __align__(16) float Bs[16][64];

    const int iy = blockIdx.x;
    const int bp = blockIdx.y;
    const int b  = bp >> 2;
    const int p  = bp & 3;
    const int py = p >> 1;
    const int px = p & 1;
    const int o0 = blockIdx.z * 64;

    const int tid = threadIdx.x;
    const int tx = tid & 15;
    const int ty = tid >> 4;
    const int nb = tx * 4;   // output-column micro-tile base
    const int mb = ty * 4;   // cout micro-tile base

    float accH[4][4] = {};
    float accL[4][4] = {};

    // Tap tables: parity = 2*d + k - 1  (k in 0..2)
    int ndy, dys[2], kys[2];
    if (py == 0) { ndy = 1; dys[0] = 0; kys[0] = 1; }
    else         { ndy = 2; dys[0] = 0; kys[0] = 2; dys[1] = 1; kys[1] = 0; }
    int ndx, dxs[2], kxs[2];
    if (px == 0) { ndx = 1; dxs[0] = 0; kxs[0] = 1; }
    else         { ndx = 2; dxs[0] = 0; kxs[0] = 2; dxs[1] = 1; kxs[1] = 0; }

    for (int ti = 0; ti < ndy; ti++) {
        const int dy = dys[ti], ky = kys[ti];
        const int yy = iy + dy;
        if (yy >= H_) continue;               // top-parity row at the boundary: tap is zero
        for (int tj = 0; tj < ndx; tj++) {
            const int dx = dxs[tj], kx = kxs[tj];
            const int t = ky * 3 + kx;

            // ---- high branch: K = CIN over inx ----
            {
                const float* WT = g_wth + t * CIN * COUT + o0;
                const float* X  = inx + ((size_t)(b * CIN) * H_ + yy) * W_;
                for (int c0 = 0; c0 < CIN; c0 += 16) {
#pragma unroll
                    for (int r = 0; r < 4; r++) {
                        int e = tid + 256 * r;
                        int k = e >> 6;
                        int m = e & 63;
                        As[k][m] = WT[(c0 + k) * COUT + m];
                        int xc = m + dx;
                        Bs[k][m] = (xc < W_) ? X[(size_t)(c0 + k) * (H_ * W_) + xc] : 0.f;
                    }
                    __syncthreads();
#pragma unroll
                    for (int k = 0; k < 16; k++) {
                        const float4 a = *(const float4*)(&As[k][mb]);
                        const float4 v = *(const float4*)(&Bs[k][nb]);
                        const float av[4] = {a.x, a.y, a.z, a.w};
                        const float bv[4] = {v.x, v.y, v.z, v.w};
#pragma unroll
                        for (int i = 0; i < 4; i++)
#pragma unroll
                            for (int j = 0; j < 4; j++)
                                accH[i][j] = fmaf(av[i], bv[j], accH[i][j]);
                    }
                    __syncthreads();
                }
            }
            // ---- low branch: K = CMID over g_mid ----
            {
                const float* WT = g_wtl + t * CMID * COUT + o0;
                const float* X  = g_mid + ((size_t)(b * CMID) * H_ + yy) * W_;
                for (int c0 = 0; c0 < CMID; c0 += 16) {
#pragma unroll
                    for (int r = 0; r < 4; r++) {
                        int e = tid + 256 * r;
                        int k = e >> 6;
                        int m = e & 63;
                        As[k][m] = WT[(c0 + k) * COUT + m];
                        int xc = m + dx;
                        Bs[k][m] = (xc < W_) ? X[(size_t)(c0 + k) * (H_ * W_) + xc] : 0.f;
                    }
                    __syncthreads();
#pragma unroll
                    for (int k = 0; k < 16; k++) {
                        const float4 a = *(const float4*)(&As[k][mb]);
                        const float4 v = *(const float4*)(&Bs[k][nb]);
                        const float av[4] = {a.x, a.y, a.z, a.w};
                        const float bv[4] = {v.x, v.y, v.z, v.w};
#pragma unroll
                        for (int i = 0; i < 4; i++)
#pragma unroll
                            for (int j = 0; j < 4; j++)
                                accL[i][j] = fmaf(av[i], bv[j], accL[i][j]);
                    }
                    __syncthreads();
                }
            }
        }
    }

    // ---- epilogue: bias + complementary mask routing ----
    const int oy = 2 * iy + py;
    const float* mrow = mask     + ((size_t)b * HO + oy) * WO;
    const float* irow = inv_mask + ((size_t)b * HO + oy) * WO;
#pragma unroll
    for (int j = 0; j < 4; j++) {
        const int n = nb + j;
        const int ox = 2 * n + px;
        const float mv = mrow[ox];
        const float iv = irow[ox];
#pragma unroll
        for (int i = 0; i < 4; i++) {
            const int o = o0 + mb + i;
            float val = (accH[i][j] + bh[o]) * mv + (accL[i][j] + bl2[o]) * iv;
            out[(((size_t)b * COUT + o) * HO + oy) * WO + ox] = val;
        }
    }
}

// ---------------------------------------------------------------------------
// Launch
// ---------------------------------------------------------------------------
extern "C" void kernel_launch(void* const* d_in, const int* in_sizes, int n_in,
                              void* d_out, int out_size) {
    const float* inx      = (const float*)d_in[0];
    const float* mask     = (const float*)d_in[1];
    const float* inv_mask = (const float*)d_in[2];
    const float* w_high   = (const float*)d_in[3];
    const float* b_high   = (const float*)d_in[4];
    const float* w_low1   = (const float*)d_in[5];
    const float* b_low1   = (const float*)d_in[6];
    const float* w_low2   = (const float*)d_in[7];
    const float* b_low2   = (const float*)d_in[8];
    float* out = (float*)d_out;

    // Kernel 0: weight transpose (9*256*256 elements dominate)
    const int NT = 9 * CIN * COUT;
    transpose_weights_kernel<<<(NT + 255) / 256, 256>>>(w_high, w_low2);

    // Kernel 1: 1x1 bottleneck -> g_mid
    mid_kernel<<<B_ * H_, 256>>>(inx, w_low1, b_low1);

    // Kernel 2: main fused transposed-conv + mask routing
    dim3 grid(H_, B_ * 4, COUT / 64);
    tconv_main_kernel<<<grid, 256>>>(inx, mask, inv_mask, b_high, b_low2, out);
}

// round 5
// speedup vs baseline: 2.0586x; 2.0586x over previous
#include <cuda_runtime.h>
#include <cstdint>

#define B_    4
#define CIN   256
#define COUT  256
#define CMID  64
#define H_    64
#define W_    64
#define HO    128
#define WO    128
#define PS    36   // padded smem row stride (words): 4g+tq conflict-free fragment loads

// ---------------------------------------------------------------------------
// Static device scratch
// ---------------------------------------------------------------------------
__device__ __align__(128) float g_xt  [B_ * H_ * W_ * CIN];   // NHWC input (tf32-rounded)
__device__ __align__(128) float g_midt[B_ * H_ * W_ * CMID];  // NHWC mid   (tf32-rounded)
__device__ __align__(128) float g_wh  [9 * COUT * CIN];       // [t][o][c]  (tf32-rounded)
__device__ __align__(128) float g_wl  [9 * COUT * CMID];      // [t][o][c]  (tf32-rounded)
__device__ __align__(128) float g_w1t [CIN * CMID];           // [c][m] fp32

__device__ __forceinline__ float tf32r(float f) {
    float r;
    asm("cvt.rna.tf32.f32 %0, %1;" : "=f"(r) : "f"(f));
    return r;
}

// ---------------------------------------------------------------------------
// Kernel: weight prep
// ---------------------------------------------------------------------------
__global__ void __launch_bounds__(256) prep_kernel(const float* __restrict__ wh,
                                                   const float* __restrict__ wl2,
                                                   const float* __restrict__ w1) {
    int i = blockIdx.x * 256 + threadIdx.x;
    if (i < 9 * COUT * CIN) {
        int t = i / (COUT * CIN); int r = i - t * (COUT * CIN);
        int o = r >> 8; int c = r & 255;
        g_wh[i] = tf32r(wh[(c * COUT + o) * 9 + t]);
    }
    if (i < 9 * COUT * CMID) {
        int t = i / (COUT * CMID); int r = i - t * (COUT * CMID);
        int o = r >> 6; int c = r & 63;
        g_wl[i] = tf32r(wl2[(c * COUT + o) * 9 + t]);
    }
    if (i < CIN * CMID) {
        int c = i >> 6; int m = i & 63;
        g_w1t[i] = w1[m * CIN + c];
    }
}

// ---------------------------------------------------------------------------
// Kernel: NCHW -> NHWC transpose of inx (tf32-rounded)
// ---------------------------------------------------------------------------
__global__ void __launch_bounds__(256) nhwc_kernel(const float* __restrict__ inx) {
    __shared__ float t[32][65];
    const int b = blockIdx.x >> 6, y = blockIdx.x & 63, tid = threadIdx.x;
    for (int cb = 0; cb < 8; cb++) {
#pragma unroll
        for (int r = 0; r < 8; r++) {
            int e = r * 256 + tid; int c = e >> 6; int x = e & 63;
            t[c][x] = inx[(((b * CIN) + cb * 32 + c) * H_ + y) * W_ + x];
        }
        __syncthreads();
#pragma unroll
        for (int r = 0; r < 8; r++) {
            int e = r * 256 + tid; int x = e >> 5; int c = e & 31;
            g_xt[((b * H_ + y) * W_ + x) * CIN + cb * 32 + c] = tf32r(t[c][x]);
        }
        __syncthreads();
    }
}

// ---------------------------------------------------------------------------
// Kernel: mid = w1 @ x + b1 in NHWC (fp32 compute, tf32-rounded store)
// ---------------------------------------------------------------------------
__global__ void __launch_bounds__(256) mid_kernel(const float* __restrict__ b1) {
    __shared__ float Xs[64][33];
    __shared__ float Ws[32][64];
    const int b = blockIdx.x >> 6, y = blockIdx.x & 63, tid = threadIdx.x;
    const int x = tid >> 2, mq = tid & 3;

    float acc[16];
#pragma unroll
    for (int i = 0; i < 16; i++) acc[i] = 0.f;

    const float* Xrow = g_xt + ((size_t)(b * H_ + y) * W_) * CIN;
    for (int c0 = 0; c0 < CIN; c0 += 32) {
#pragma unroll
        for (int r = 0; r < 8; r++) {
            int e = r * 256 + tid; int xr = e >> 5; int c = e & 31;
            Xs[xr][c] = Xrow[xr * CIN + c0 + c];
            Ws[c][xr] = g_w1t[(c0 + c) * CMID + xr];
        }
        __syncthreads();
#pragma unroll
        for (int c = 0; c < 32; c++) {
            float xv = Xs[x][c];
#pragma unroll
            for (int i = 0; i < 16; i++)
                acc[i] = fmaf(Ws[c][mq * 16 + i], xv, acc[i]);
        }
        __syncthreads();
    }
    float* dst = g_midt + ((size_t)((b * H_ + y) * W_ + x)) * CMID + mq * 16;
#pragma unroll
    for (int i = 0; i < 16; i++) dst[i] = tf32r(acc[i] + b1[mq * 16 + i]);
}

// ---------------------------------------------------------------------------
// One K=32 chunk: cooperative load A[128x32], B[64x32] then warp HMMA tf32.
// ---------------------------------------------------------------------------
__device__ __forceinline__ void gemm_chunk(
    float* As, float* Bs,
    const float* __restrict__ Wt, int ldw,     // weights, c0 pre-applied
    const float* __restrict__ Xr, int ldx,     // NHWC pixels, c0 pre-applied
    int dx,
    float acc[8][4], int wm, int wn, int lane, int tid)
{
    // A: 128 rows x 32 ch (8 float4/row), 4 float4 per thread
#pragma unroll
    for (int r = 0; r < 4; r++) {
        int e = r * 256 + tid; int o = e >> 3; int f4 = e & 7;
        float4 v = *(const float4*)(Wt + o * ldw + f4 * 4);
        *(float4*)&As[o * PS + f4 * 4] = v;
    }
    // B: 64 pixels x 32 ch, 2 float4 per thread (zero-fill past right edge)
#pragma unroll
    for (int r = 0; r < 2; r++) {
        int e = r * 256 + tid; int ix = e >> 3; int f4 = e & 7;
        int xx = ix + dx;
        float4 v = make_float4(0.f, 0.f, 0.f, 0.f);
        if (xx < W_) v = *(const float4*)(Xr + (size_t)xx * ldx + f4 * 4);
        *(float4*)&Bs[ix * PS + f4 * 4] = v;
    }
    __syncthreads();

    const int g = lane >> 2, tq = lane & 3;
#pragma unroll
    for (int kk = 0; kk < 4; kk++) {
        const int kb = kk * 8;
        uint32_t a[2][4], bf[4][2];
#pragma unroll
        for (int i = 0; i < 2; i++) {
            int m = wm + i * 16 + g;
            a[i][0] = __float_as_uint(As[m * PS + kb + tq]);
            a[i][1] = __float_as_uint(As[(m + 8) * PS + kb + tq]);
            a[i][2] = __float_as_uint(As[m * PS + kb + tq + 4]);
            a[i][3] = __float_as_uint(As[(m + 8) * PS + kb + tq + 4]);
        }
#pragma unroll
        for (int j = 0; j < 4; j++) {
            int n = wn + j * 8 + g;
            bf[j][0] = __float_as_uint(Bs[n * PS + kb + tq]);
            bf[j][1] = __float_as_uint(Bs[n * PS + kb + tq + 4]);
        }
#pragma unroll
        for (int i = 0; i < 2; i++)
#pragma unroll
            for (int j = 0; j < 4; j++) {
                float* c = acc[i * 4 + j];
                asm volatile(
                    "mma.sync.aligned.m16n8k8.row.col.f32.tf32.tf32.f32 "
                    "{%0,%1,%2,%3}, {%4,%5,%6,%7}, {%8,%9}, {%0,%1,%2,%3};"
                    : "+f"(c[0]), "+f"(c[1]), "+f"(c[2]), "+f"(c[3])
                    : "r"(a[i][0]), "r"(a[i][1]), "r"(a[i][2]), "r"(a[i][3]),
                      "r"(bf[j][0]), "r"(bf[j][1]));
            }
    }
    __syncthreads();
}

// ---------------------------------------------------------------------------
// Main: HMMA tf32 implicit GEMM, parity-decomposed transposed conv.
// CTA = (iy, b*4+parity, cout-half). M=128, N=64 (one output row of parity p).
// ---------------------------------------------------------------------------
__global__ void __launch_bounds__(256, 2) tconv_hmma_kernel(
    const float* __restrict__ mask, const float* __restrict__ inv_mask,
    const float* __restrict__ bh, const float* __restrict__ bl,
    float* __restrict__ out)
{
    __shared__ __align__(16) float As[128 * PS];
    __shared__ __align__(16) float Bs[64 * PS];

    const int tid = threadIdx.x, wid = tid >> 5, lane = tid & 31;
    const int iy = blockIdx.x;
    const int bp = blockIdx.y;
    const int b = bp >> 2, p = bp & 3;
    const int py = p >> 1, px = p & 1;
    const int oh = blockIdx.z;

    const int wm = (wid & 3) * 32;   // warp m base in [0,128)
    const int wn = (wid >> 2) * 32;  // warp n base in [0,64)

    float accH[8][4] = {};
    float accL[8][4] = {};

    // Tap tables: parity = 2*d + k - 1
    int ndy, dys[2], kys[2];
    if (py == 0) { ndy = 1; dys[0] = 0; kys[0] = 1; }
    else         { ndy = 2; dys[0] = 0; kys[0] = 2; dys[1] = 1; kys[1] = 0; }
    int ndx, dxs[2], kxs[2];
    if (px == 0) { ndx = 1; dxs[0] = 0; kxs[0] = 1; }
    else         { ndx = 2; dxs[0] = 0; kxs[0] = 2; dxs[1] = 1; kxs[1] = 0; }

    for (int ti = 0; ti < ndy; ti++) {
        const int dy = dys[ti], ky = kys[ti];
        const int yy = iy + dy;
        if (yy >= H_) continue;
        for (int tj = 0; tj < ndx; tj++) {
            const int dx = dxs[tj], kx = kxs[tj];
            const int t = ky * 3 + kx;

            // high branch: K = 256
            {
                const float* Wh = g_wh + (size_t)t * (COUT * CIN) + (size_t)oh * 128 * CIN;
                const float* Xr = g_xt + ((size_t)(b * H_ + yy) * W_) * CIN;
#pragma unroll 1
                for (int c0 = 0; c0 < CIN; c0 += 32)
                    gemm_chunk(As, Bs, Wh + c0, CIN, Xr + c0, CIN, dx,
                               accH, wm, wn, lane, tid);
            }
            // low branch: K = 64
            {
                const float* Wl = g_wl + (size_t)t * (COUT * CMID) + (size_t)oh * 128 * CMID;
                const float* Xm = g_midt + ((size_t)(b * H_ + yy) * W_) * CMID;
#pragma unroll 1
                for (int c0 = 0; c0 < CMID; c0 += 32)
                    gemm_chunk(As, Bs, Wl + c0, CMID, Xm + c0, CMID, dx,
                               accL, wm, wn, lane, tid);
            }
        }
    }

    // ---- Epilogue: bias + complementary mask routing, direct stores ----
    const int oy = 2 * iy + py;
    const float* mrow = mask     + ((size_t)b * HO + oy) * WO;
    const float* irow = inv_mask + ((size_t)b * HO + oy) * WO;
    const int g = lane >> 2, tq = lane & 3;

#pragma unroll
    for (int i = 0; i < 2; i++) {
        const int o0 = oh * 128 + wm + i * 16 + g;
        const float bh0 = bh[o0], bh8 = bh[o0 + 8];
        const float bl0 = bl[o0], bl8 = bl[o0 + 8];
        float* r0 = out + (((size_t)(b * COUT + o0)) * HO + oy) * WO + px;
        float* r8 = out + (((size_t)(b * COUT + o0 + 8)) * HO + oy) * WO + px;
#pragma unroll
        for (int j = 0; j < 4; j++) {
            const int n0 = wn + j * 8 + tq * 2;
            const int x0 = 2 * n0, x1 = 2 * n0 + 2;
            const float m0 = mrow[x0 + px], m1 = mrow[x1 + px];
            const float i0 = irow[x0 + px], i1 = irow[x1 + px];
            const float* cH = accH[i * 4 + j];
            const float* cL = accL[i * 4 + j];
            r0[x0] = (cH[0] + bh0) * m0 + (cL[0] + bl0) * i0;
            r0[x1] = (cH[1] + bh0) * m1 + (cL[1] + bl0) * i1;
            r8[x0] = (cH[2] + bh8) * m0 + (cL[2] + bl8) * i0;
            r8[x1] = (cH[3] + bh8) * m1 + (cL[3] + bl8) * i1;
        }
    }
}

// ---------------------------------------------------------------------------
// Launch
// ---------------------------------------------------------------------------
extern "C" void kernel_launch(void* const* d_in, const int* in_sizes, int n_in,
                              void* d_out, int out_size) {
    const float* inx      = (const float*)d_in[0];
    const float* mask     = (const float*)d_in[1];
    const float* inv_mask = (const float*)d_in[2];
    const float* w_high   = (const float*)d_in[3];
    const float* b_high   = (const float*)d_in[4];
    const float* w_low1   = (const float*)d_in[5];
    const float* b_low1   = (const float*)d_in[6];
    const float* w_low2   = (const float*)d_in[7];
    const float* b_low2   = (const float*)d_in[8];
    float* out = (float*)d_out;

    prep_kernel<<<(9 * COUT * CIN + 255) / 256, 256>>>(w_high, w_low2, w_low1);
    nhwc_kernel<<<B_ * H_, 256>>>(inx);
    mid_kernel<<<B_ * H_, 256>>>(b_low1);

    dim3 grid(H_, B_ * 4, 2);
    tconv_hmma_kernel<<<grid, 256>>>(mask, inv_mask, b_high, b_low2, out);
}